// round 2
// baseline (speedup 1.0000x reference)
#include <cuda_runtime.h>
#include <math.h>

#define NW 22

// Tables built by setup kernel, consumed by main kernel.
__device__ __align__(16) float gTA[1024];   // wires 2..10 product (x*y), indexed by c_1..c_10
__device__ __align__(16) float gTB[1024];   // wires 11..19 product (x*y), indexed by c_10..c_19
__device__ __align__(16) float gS[32];      // |sum_k tail_y*tail_x|, key=(c19<<4)|(c0<<3)|(c1<<2)|(i<<1)|j

__global__ void __launch_bounds__(256) qk_setup(const float* __restrict__ x,
                                                const float* __restrict__ y) {
    __shared__ double cx[NW], sx[NW], cy[NW], sy[NW];
    int t = threadIdx.x;
    if (t < NW) {
        double hx = 0.5 * (double)x[t];
        double hy = 0.5 * (double)y[t];
        cx[t] = cos(hx); sx[t] = sin(hx);
        cy[t] = cos(hy); sy[t] = sin(hy);
    }
    __syncthreads();

    for (int v = t; v < 1024; v += 256) {
        // --- TA: wires 2..10, needs c_1..c_10.  Layout: bit tt of v = c_{10-tt}.
        {
            int c[11];
            #pragma unroll
            for (int tt = 0; tt <= 9; ++tt) c[10 - tt] = (v >> tt) & 1;
            double px = 1.0, py = 1.0;
            #pragma unroll
            for (int w = 2; w <= 10; ++w) {
                int bw = c[w - 1] ^ c[w];
                px *= bw ? sx[w] : cx[w];
                py *= bw ? sy[w] : cy[w];
            }
            gTA[v] = (float)(px * py);
        }
        // --- TB: wires 11..19, needs c_10..c_19.  Layout: bit tt of v = c_{19-tt}.
        {
            int c[20];
            #pragma unroll
            for (int tt = 0; tt <= 9; ++tt) c[19 - tt] = (v >> tt) & 1;
            double px = 1.0, py = 1.0;
            #pragma unroll
            for (int w = 11; w <= 19; ++w) {
                int bw = c[w - 1] ^ c[w];
                px *= bw ? sx[w] : cx[w];
                py *= bw ? sy[w] : cy[w];
            }
            gTB[v] = (float)(px * py);
        }
    }

    // --- S table: pre-contracted 2x2 matmul tail + abs.
    // Y amplitude index: c20=i, c21=k ; X amplitude index: c20=k, c21=j.
    // tail(state; c19,c20,c21,c0,c1) = a20(c19^c20)*a21(c20^c21)*a0(c0^c21)*a1(c0^c1^c21)
    if (t < 32) {
        int j   =  t        & 1;
        int i   = (t >> 1)  & 1;
        int c1  = (t >> 2)  & 1;
        int c0  = (t >> 3)  & 1;
        int c19 = (t >> 4)  & 1;
        double s = 0.0;
        #pragma unroll
        for (int k = 0; k < 2; ++k) {
            double ty = ((c19 ^ i)      ? sy[20] : cy[20])
                      * ((i   ^ k)      ? sy[21] : cy[21])
                      * ((c0  ^ k)      ? sy[0]  : cy[0])
                      * ((c0 ^ c1 ^ k)  ? sy[1]  : cy[1]);
            double tx = ((c19 ^ k)      ? sx[20] : cx[20])
                      * ((k   ^ j)      ? sx[21] : cx[21])
                      * ((c0  ^ j)      ? sx[0]  : cx[0])
                      * ((c0 ^ c1 ^ j)  ? sx[1]  : cx[1]);
            s += ty * tx;
        }
        gS[t] = (float)fabs(s);
    }
}

// One thread per batch b (20 bits). Index bit map: c_w = bit(19-w) of b for w<=19.
//   va = (b>>9)&1023  -> bit t = c_{10-t}   (matches gTA layout)
//   vb =  b     &1023 -> bit t = c_{19-t}   (matches gTB layout; consecutive lanes coalesce)
//   c19 = b&1, c0 = (b>>19)&1, c1 = (b>>18)&1
__global__ void __launch_bounds__(256) qk_main(float4* __restrict__ out) {
    unsigned b = blockIdx.x * blockDim.x + threadIdx.x;
    float A = __ldg(&gTA[(b >> 9) & 1023u]);
    float B = __ldg(&gTB[b & 1023u]);
    float m = fabsf(A * B);
    unsigned c19 = b & 1u;
    unsigned c0  = (b >> 19) & 1u;
    unsigned c1  = (b >> 18) & 1u;
    const float4* S4 = reinterpret_cast<const float4*>(gS);
    float4 s = __ldg(&S4[(c19 << 2) | (c0 << 1) | c1]);
    float4 o;
    o.x = m * s.x;
    o.y = m * s.y;
    o.z = m * s.z;
    o.w = m * s.w;
    out[b] = o;
}

extern "C" void kernel_launch(void* const* d_in, const int* in_sizes, int n_in,
                              void* d_out, int out_size) {
    const float* x = (const float*)d_in[0];
    const float* y = (const float*)d_in[1];
    qk_setup<<<1, 256>>>(x, y);
    // 2^22 outputs = 2^20 float4 stores; 256 threads/block -> 4096 blocks
    qk_main<<<4096, 256>>>((float4*)d_out);
}

// round 3
// speedup vs baseline: 2.7463x; 2.7463x over previous
#include <cuda_runtime.h>
#include <math.h>

#define NW 22

// Fully fused: each block rebuilds the tiny factor tables in shared memory
// (fp32, fast trig), then writes its 1024 float4 outputs.
//
// Math (validated in R2 at rel_err 1.8e-7):
//   out[4b+2i+j] = |TA[(b>>9)&1023] * TB[b&1023]| * S[c19,c0,c1,i,j]
//   c19 = b&1, c0 = (b>>19)&1, c1 = (b>>18)&1
//   TA indexed by c_1..c_10 (bit t of v = c_{10-t}),  wires 2..10
//   TB indexed by c_10..c_19 (bit t of v = c_{19-t}), wires 11..19
//   b_w = c_{w-1} ^ c_w  ->  adjacent-bit XOR of v:  u = v ^ (v>>1)

__global__ void __launch_bounds__(256) qk_fused(const float* __restrict__ x,
                                                const float* __restrict__ y,
                                                float4* __restrict__ out) {
    __shared__ float cx[NW], sx[NW], cy[NW], sy[NW];
    __shared__ float pc[NW], ps[NW];        // pair products cx*cy, sx*sy
    __shared__ float sTA[1024], sTB[1024];
    __shared__ float4 sS[8];                // [c19][c0][c1] -> 4 outputs (i,j)
    int t = threadIdx.x;

    if (t < NW) {
        float sxx, cxx, syy, cyy;
        __sincosf(0.5f * x[t], &sxx, &cxx);
        __sincosf(0.5f * y[t], &syy, &cyy);
        cx[t] = cxx; sx[t] = sxx; cy[t] = cyy; sy[t] = syy;
        pc[t] = cxx * cyy; ps[t] = sxx * syy;
    }
    __syncthreads();

    // Fill TA/TB: 4 entries each per thread.
    #pragma unroll
    for (int i = 0; i < 4; ++i) {
        int v = t + (i << 8);
        int u = v ^ (v >> 1);
        float a = 1.0f, bb = 1.0f;
        #pragma unroll
        for (int j = 0; j < 9; ++j) {
            bool bit = (u >> j) & 1;
            a  *= bit ? ps[10 - j] : pc[10 - j];   // wire w = 10-j  (2..10)
            bb *= bit ? ps[19 - j] : pc[19 - j];   // wire w = 19-j  (11..19)
        }
        sTA[v] = a;
        sTB[v] = bb;
    }

    // S table: pre-contracted 2x2 matmul tail + abs (32 scalars).
    if (t < 32) {
        int j   =  t        & 1;
        int i   = (t >> 1)  & 1;
        int c1  = (t >> 2)  & 1;
        int c0  = (t >> 3)  & 1;
        int c19 = (t >> 4)  & 1;
        float s = 0.0f;
        #pragma unroll
        for (int k = 0; k < 2; ++k) {
            float ty = ((c19 ^ i)     ? sy[20] : cy[20])
                     * ((i   ^ k)     ? sy[21] : cy[21])
                     * ((c0  ^ k)     ? sy[0]  : cy[0])
                     * ((c0 ^ c1 ^ k) ? sy[1]  : cy[1]);
            float tx = ((c19 ^ k)     ? sx[20] : cx[20])
                     * ((k   ^ j)     ? sx[21] : cx[21])
                     * ((c0  ^ j)     ? sx[0]  : cx[0])
                     * ((c0 ^ c1 ^ j) ? sx[1]  : cx[1]);
            s += ty * tx;
        }
        reinterpret_cast<float*>(sS)[t] = fabsf(s);
    }
    __syncthreads();

    // Main loop: 4 coalesced float4 stores per thread.
    unsigned base = (unsigned)blockIdx.x << 10;
    #pragma unroll
    for (int k = 0; k < 4; ++k) {
        unsigned b = base + (unsigned)(k << 8) + (unsigned)t;
        float A = sTA[(b >> 9) & 1023u];   // warp-uniform broadcast
        float B = sTB[b & 1023u];          // lane-consecutive, conflict-free
        float m = fabsf(A * B);
        float4 s = sS[((b & 1u) << 2) | (((b >> 19) & 1u) << 1) | ((b >> 18) & 1u)];
        float4 o;
        o.x = m * s.x; o.y = m * s.y; o.z = m * s.z; o.w = m * s.w;
        out[b] = o;
    }
}

extern "C" void kernel_launch(void* const* d_in, const int* in_sizes, int n_in,
                              void* d_out, int out_size) {
    const float* x = (const float*)d_in[0];
    const float* y = (const float*)d_in[1];
    // 2^20 float4 outputs / (256 threads * 4 per thread) = 1024 blocks
    qk_fused<<<1024, 256>>>(x, y, (float4*)d_out);
}

// round 4
// speedup vs baseline: 2.7667x; 1.0074x over previous
#include <cuda_runtime.h>
#include <math.h>

#define NW 22

// Single-wave fused kernel: 128 blocks x 1024 threads, 8 float4 outputs/thread.
//
// Math (validated R2/R3):
//   out[4b+2i+j] = |TA[(b>>9)&1023] * TB[b&1023]| * S[c19,c0,c1,i,j]
//   c19=b&1, c0=(b>>19)&1, c1=(b>>18)&1
//   TA indexed by c_1..c_10 (bit t = c_{10-t}),  wires 2..10
//   TB indexed by c_10..c_19 (bit t = c_{19-t}), wires 11..19
//   b_w = c_{w-1}^c_w  ->  u = v ^ (v>>1)
//
// Decomposition per thread (b = (blk<<13)+(k<<10)+t):
//   B-index = b & 1023 = t                      -> k-invariant, load once
//   sS-index uses bits 0,18,19 of b             -> k-invariant, load once
//   A-index = (b>>9)&1023, warp-uniform         -> 1 broadcast LDS per k

__global__ void __launch_bounds__(1024) qk_fused(const float* __restrict__ x,
                                                 const float* __restrict__ y,
                                                 float4* __restrict__ out) {
    __shared__ float cx[NW], sx[NW], cy[NW], sy[NW];
    __shared__ float pc[NW], ps[NW];       // pair products cx*cy, sx*sy
    __shared__ float sTA[1024], sTB[1024];
    __shared__ float4 sS[8];               // [c19][c0][c1] -> (i,j) quad
    const int t = threadIdx.x;

    if (t < NW) {
        float sxx, cxx, syy, cyy;
        __sincosf(0.5f * x[t], &sxx, &cxx);
        __sincosf(0.5f * y[t], &syy, &cyy);
        cx[t] = cxx; sx[t] = sxx; cy[t] = cyy; sy[t] = syy;
        pc[t] = cxx * cyy; ps[t] = sxx * syy;
    }
    __syncthreads();

    // Each thread fills one entry of each table.
    {
        int u = t ^ (t >> 1);
        float a = 1.0f, bb = 1.0f;
        #pragma unroll
        for (int j = 0; j < 9; ++j) {
            bool bit = (u >> j) & 1;
            a  *= bit ? ps[10 - j] : pc[10 - j];   // wires 2..10
            bb *= bit ? ps[19 - j] : pc[19 - j];   // wires 11..19
        }
        sTA[t] = a;
        sTB[t] = bb;
    }

    // S table: pre-contracted 2x2 matmul tail + abs (32 scalars).
    if (t < 32) {
        int j   =  t        & 1;
        int i   = (t >> 1)  & 1;
        int c1  = (t >> 2)  & 1;
        int c0  = (t >> 3)  & 1;
        int c19 = (t >> 4)  & 1;
        float s = 0.0f;
        #pragma unroll
        for (int k = 0; k < 2; ++k) {
            float ty = ((c19 ^ i)     ? sy[20] : cy[20])
                     * ((i   ^ k)     ? sy[21] : cy[21])
                     * ((c0  ^ k)     ? sy[0]  : cy[0])
                     * ((c0 ^ c1 ^ k) ? sy[1]  : cy[1]);
            float tx = ((c19 ^ k)     ? sx[20] : cx[20])
                     * ((k   ^ j)     ? sx[21] : cx[21])
                     * ((c0  ^ j)     ? sx[0]  : cx[0])
                     * ((c0 ^ c1 ^ j) ? sx[1]  : cx[1]);
            s += ty * tx;
        }
        reinterpret_cast<float*>(sS)[t] = fabsf(s);
    }
    __syncthreads();

    // Main loop: 8 coalesced float4 stores per thread.
    const unsigned base = (unsigned)blockIdx.x << 13;
    const float B = sTB[t];                                     // b&1023 == t
    const unsigned b0 = base + (unsigned)t;
    const float4 s = sS[((b0 & 1u) << 2) | (((b0 >> 19) & 1u) << 1)
                        | ((b0 >> 18) & 1u)];                   // k-invariant
    const float Bsx = B * s.x, Bsy = B * s.y, Bsz = B * s.z, Bsw = B * s.w;

    #pragma unroll
    for (int k = 0; k < 8; ++k) {
        unsigned b = b0 + ((unsigned)k << 10);
        float A = fabsf(sTA[(b >> 9) & 1023u]);                 // warp-uniform LDS
        float4 o;
        o.x = fabsf(A * Bsx);
        o.y = fabsf(A * Bsy);
        o.z = fabsf(A * Bsz);
        o.w = fabsf(A * Bsw);
        out[b] = o;
    }
}

extern "C" void kernel_launch(void* const* d_in, const int* in_sizes, int n_in,
                              void* d_out, int out_size) {
    const float* x = (const float*)d_in[0];
    const float* y = (const float*)d_in[1];
    // 2^20 float4 outputs / (1024 threads * 8 per thread) = 128 blocks
    qk_fused<<<128, 1024>>>(x, y, (float4*)d_out);
}